// round 7
// baseline (speedup 1.0000x reference)
#include <cuda_runtime.h>
#include <cuda_fp16.h>

// Problem constants (fixed by the dataset):
//   x:     (B, 3)  float32, B = 131072
//   knots: (3, 48) float32   (uniform linspace per dim -> a=b=0.5 tangents)
//   grid:  (48, 48, 48, 16) float32
//   out:   (B, 16) float32
#define NK 48
#define NP 50          // padded extent (NK + 2)
#define KP 52          // per-copy padded k extent (keeps rows 128B aligned)
#define NV 16

// Four k-shifted fp16 copies of the padded grid. Copy c holds padded value
// (I,J,k'+c,v) at (I,J,k',v). For a row starting at padded k=b2, copy c=b2&3
// at k'=b2-c makes the 4k x 16ch x 2B = 128B row exactly one cache line.
#define COPYSZ (NP * NP * KP * NV)
__device__ __align__(256) __half g_pad4[4 * COPYSZ];   // 16.64 MB

// ---------------------------------------------------------------------------
// Kernel 1: padded grid (linear extrapolation per axis) into 4 fp16 copies.
// 2 threads per cell (each owns 8 channels).
// ---------------------------------------------------------------------------
__device__ __forceinline__ int pad_terms(int I, int* s, float* c) {
    if (I == 0)      { s[0] = 0;      c[0] = 2.0f; s[1] = 1;      c[1] = -1.0f; return 2; }
    if (I == NP - 1) { s[0] = NK - 1; c[0] = 2.0f; s[1] = NK - 2; c[1] = -1.0f; return 2; }
    s[0] = I - 1; c[0] = 1.0f; return 1;
}

__global__ void pad_kernel(const float* __restrict__ grid) {
    int tid = blockIdx.x * blockDim.x + threadIdx.x;
    const int TOT = NP * NP * NP;
    int idx  = tid >> 1;
    int half = tid & 1;
    if (idx >= TOT) return;
    int K = idx % NP;
    int t = idx / NP;
    int J = t % NP;
    int I = t / NP;

    int si[2], sj[2], skk[2];
    float ci[2], cj[2], ck[2];
    int ni = pad_terms(I, si, ci);
    int nj = pad_terms(J, sj, cj);
    int nk = pad_terms(K, skk, ck);

    float v[8];
    #pragma unroll
    for (int q = 0; q < 8; q++) v[q] = 0.0f;

    for (int a = 0; a < ni; a++)
        for (int b = 0; b < nj; b++)
            for (int c = 0; c < nk; c++) {
                float w = ci[a] * cj[b] * ck[c];
                const float* src = grid + ((si[a] * NK + sj[b]) * NK + skk[c]) * NV + half * 8;
                #pragma unroll
                for (int q = 0; q < 8; q++) v[q] += w * src[q];
            }

    __half2 h[4];
    #pragma unroll
    for (int q = 0; q < 4; q++)
        h[q] = __halves2half2(__float2half_rn(v[2 * q]), __float2half_rn(v[2 * q + 1]));
    const uint4 hv = *reinterpret_cast<const uint4*>(h);

    #pragma unroll
    for (int c = 0; c < 4; c++) {
        int kp = K - c;
        if (kp >= 0) {
            uint4* dst = reinterpret_cast<uint4*>(
                g_pad4 + c * COPYSZ + ((I * NP + J) * KP + kp) * NV + half * 8);
            *dst = hv;
        }
    }
}

// ---------------------------------------------------------------------------
// Kernel 2: 8 lanes per point; lane l owns (k = l>>1, channel half l&1).
// No broadcast shuffles: every lane computes all 3 dims' weights redundantly.
// All 16 gather loads forced in-flight via ordered asm volatile (MLP = 16).
// j-contraction in fp16 (HFMA2), i + k in packed f32x2.
// ---------------------------------------------------------------------------
__device__ __forceinline__ unsigned long long pack_f32x2(float lo, float hi) {
    unsigned long long r;
    asm("mov.b64 %0, {%1, %2};" : "=l"(r) : "f"(lo), "f"(hi));
    return r;
}

__global__ __launch_bounds__(256, 2)
void interp_kernel(const float* __restrict__ x,
                   const float* __restrict__ knots,
                   float4* __restrict__ out, int B) {
    const int tid = threadIdx.x;
    const int l   = tid & 7;
    const int p   = blockIdx.x * 32 + (tid >> 3);   // B % 32 == 0

    // ---- per-lane full weight computation (no broadcasts needed) ----
    float w0[4], w1[4], w2[4];
    int bidx[3];
    {
        float* wall[3] = {w0, w1, w2};
        #pragma unroll
        for (int d = 0; d < 3; d++) {
            const float xd = __ldg(x + p * 3 + d);
            const float k0 = __ldg(knots + d * NK);
            const float kN = __ldg(knots + d * NK + NK - 1);
            const float t  = (xd - k0) * __fdividef((float)(NK - 1), kN - k0);
            int idx = __float2int_rd(t);
            idx = idx < 0 ? 0 : (idx > NK - 2 ? NK - 2 : idx);
            const float u  = t - (float)idx;
            const float u2 = u * u;
            const float u3 = u2 * u;
            wall[d][0] = -0.5f * u3 +        u2 - 0.5f * u;
            wall[d][1] =  1.5f * u3 - 2.5f * u2 + 1.0f;
            wall[d][2] = -1.5f * u3 + 2.0f * u2 + 0.5f * u;
            wall[d][3] =  0.5f * u3 - 0.5f * u2;
            bidx[d] = idx;
        }
    }
    const int b0 = bidx[0], b1 = bidx[1], b2 = bidx[2];

    const int kk = l >> 1;
    const float wk = (kk == 0) ? w2[0] : (kk == 1) ? w2[1] : (kk == 2) ? w2[2] : w2[3];

    __half2 w1h[4];
    #pragma unroll
    for (int j = 0; j < 4; j++) w1h[j] = __float2half2_rn(w1[j]);

    // ---- line-aligned base in the k-shifted copy ----
    const int c     = b2 & 3;
    const int kbase = b2 & ~3;
    const __half* base = g_pad4 + c * COPYSZ
                       + ((b0 * NP + b1) * KP + kbase) * NV + l * 8;
    const int strideI = NP * KP * NV;   // halves
    const int strideJ = KP * NV;

    // ---- 16 gather loads, forced front-batch (ordered volatile asm) ----
    uint4 r[16];
    {
        unsigned long long ga = __cvta_generic_to_global(base);
        #pragma unroll
        for (int i = 0; i < 4; i++) {
            #pragma unroll
            for (int j = 0; j < 4; j++) {
                unsigned long long a = ga + (unsigned long long)((i * strideI + j * strideJ) * 2);
                uint4& rr = r[i * 4 + j];
                asm volatile("ld.global.nc.v4.u32 {%0,%1,%2,%3}, [%4];"
                             : "=r"(rr.x), "=r"(rr.y), "=r"(rr.z), "=r"(rr.w)
                             : "l"(a));
            }
        }
    }

    // ---- math: j in fp16, i in packed f32x2 ----
    unsigned long long acc2[4];
    #pragma unroll
    for (int i = 0; i < 4; i++) {
        const __half2* h0 = reinterpret_cast<const __half2*>(&r[i * 4 + 0]);
        const __half2* h1 = reinterpret_cast<const __half2*>(&r[i * 4 + 1]);
        const __half2* h2 = reinterpret_cast<const __half2*>(&r[i * 4 + 2]);
        const __half2* h3 = reinterpret_cast<const __half2*>(&r[i * 4 + 3]);

        const float wi = w0[i] * wk;
        const unsigned long long wi2 = pack_f32x2(wi, wi);

        #pragma unroll
        for (int q = 0; q < 4; q++) {
            __half2 hacc = __hmul2(w1h[0], h0[q]);
            hacc = __hfma2(w1h[1], h1[q], hacc);
            hacc = __hfma2(w1h[2], h2[q], hacc);
            hacc = __hfma2(w1h[3], h3[q], hacc);
            float2 f = __half22float2(hacc);
            unsigned long long fv = pack_f32x2(f.x, f.y);
            if (i == 0) {
                asm("mul.rn.f32x2 %0, %1, %2;" : "=l"(acc2[q]) : "l"(fv), "l"(wi2));
            } else {
                asm("fma.rn.f32x2 %0, %1, %2, %0;" : "+l"(acc2[q]) : "l"(fv), "l"(wi2));
            }
        }
    }

    // ---- reduce over k: lanes {l, l^2, l^4} share the same channel half ----
    const unsigned FULL = 0xffffffffu;
    #pragma unroll
    for (int q = 0; q < 4; q++) {
        unsigned long long o = __shfl_xor_sync(FULL, acc2[q], 2);
        asm("add.rn.f32x2 %0, %0, %1;" : "+l"(acc2[q]) : "l"(o));
    }
    #pragma unroll
    for (int q = 0; q < 4; q++) {
        unsigned long long o = __shfl_xor_sync(FULL, acc2[q], 4);
        asm("add.rn.f32x2 %0, %0, %1;" : "+l"(acc2[q]) : "l"(o));
    }

    if (l < 2) {
        float rr[8];
        #pragma unroll
        for (int q = 0; q < 4; q++)
            asm("mov.b64 {%0, %1}, %2;" : "=f"(rr[2 * q]), "=f"(rr[2 * q + 1]) : "l"(acc2[q]));
        out[p * 4 + l * 2]     = make_float4(rr[0], rr[1], rr[2], rr[3]);
        out[p * 4 + l * 2 + 1] = make_float4(rr[4], rr[5], rr[6], rr[7]);
    }
}

extern "C" void kernel_launch(void* const* d_in, const int* in_sizes, int n_in,
                              void* d_out, int out_size) {
    const float* x     = (const float*)d_in[0];   // (B, 3)
    const float* knots = (const float*)d_in[1];   // (3, 48)
    const float* grid  = (const float*)d_in[2];   // (48, 48, 48, 16)
    float4* out = (float4*)d_out;                 // (B, 16)

    int B = in_sizes[0] / 3;

    const int TOT = NP * NP * NP;
    int pad_threads = TOT * 2;
    pad_kernel<<<(pad_threads + 255) / 256, 256>>>(grid);

    long threads = (long)B * 8;
    int blocks = (int)((threads + 255) / 256);
    interp_kernel<<<blocks, 256>>>(x, knots, out, B);
}